// round 8
// baseline (speedup 1.0000x reference)
#include <cuda_runtime.h>
#include <cuda_bf16.h>
#include <cstdint>

// ============================================================================
// VA_Aggregator via mma.sync bf16 HMMA (sm_103 baseline PTX; no tcgen05).
// K0a/b/c: pre-convert W1/W2 -> bf16 interleaved SMEM-images, pack biases.
//   (3 prep launches keep mlp_score_kernel at global launch #4 = ncu window.)
// K1 (persistent, warp-autonomous, 32 ROWS PER WARP): each warp owns an
//     independent 32-row tile (two 16-row MMA sub-tiles). One weight-fragment
//     LDS feeds two MMAs -> halves weight LDS bytes per row (the R7 profile
//     showed L1/shared at 71% = binding pipe). No __syncthreads in main loop.
// K2: per-node softmax over L=50 + fp32 weighted gather of e_va (LDG.64).
// ============================================================================

constexpr int L      = 50;
constexpr int D      = 64;
constexpr int K1     = 192;
constexpr int NMAX_ROWS = 8192 * 50;
constexpr int GRID1   = 296;
constexpr int WARPS1  = 5;
constexpr int THREADS1 = 32 * WARPS1;          // 160
constexpr int ROWS_W  = 32;                    // rows per warp tile

__device__ float g_scores[NMAX_ROWS];
__device__ float g_bias[256];                  // [0:64)=b1 [64:128)=b2 [128:192)=w3 [192]=b3

// ---- SMEM layout (bytes from dynamic smem base) ----
constexpr int A_STRIDE  = 400;                 // 192*2 + 16 pad (ldsm conflict-free)
constexpr int W1_STRIDE = 416;                 // 104 words ≡ 8 mod 32 (conflict-free)
constexpr int W2_STRIDE = 160;                 // 40 words  ≡ 8 mod 32
constexpr int W1_BYTES  = 64 * W1_STRIDE;      // 26624
constexpr int W2_BYTES  = 64 * W2_STRIDE;      // 10240
constexpr int A_BYTES   = WARPS1 * ROWS_W * A_STRIDE;   // 64000
constexpr int OFF_A    = 0;
constexpr int OFF_W1   = A_BYTES;                        // 64000
constexpr int OFF_W2   = OFF_W1 + W1_BYTES;              // 90624
constexpr int OFF_BIAS = OFF_W2 + W2_BYTES;              // 100864
constexpr int SMEM_BYTES = OFF_BIAS + 1024 + 32;         // ~101920

__device__ __align__(16) uint8_t g_w1img[W1_BYTES];
__device__ __align__(16) uint8_t g_w2img[W2_BYTES];

__device__ __forceinline__ uint32_t smem_u32(const void* p) {
    uint32_t a;
    asm("{ .reg .u64 t; cvta.to.shared.u64 t, %1; cvt.u32.u64 %0, t; }"
        : "=r"(a) : "l"(p));
    return a;
}

#define CVT_BF16X2(res, lo, hi) \
    asm("cvt.rn.satfinite.bf16x2.f32 %0, %1, %2;" : "=r"(res) : "f"(hi), "f"(lo))

#define LDSM_X4(r0, r1, r2, r3, addr) \
    asm volatile("ldmatrix.sync.aligned.m8n8.x4.shared.b16 {%0,%1,%2,%3}, [%4];" \
                 : "=r"(r0), "=r"(r1), "=r"(r2), "=r"(r3) : "r"(addr))

#define LDS_V2(r0, r1, addr) \
    asm volatile("ld.shared.v2.u32 {%0,%1}, [%2];" \
                 : "=r"(r0), "=r"(r1) : "r"(addr))

#define MMA_16816(c, a, b0, b1) \
    asm volatile("mma.sync.aligned.m16n8k16.row.col.f32.bf16.bf16.f32 " \
                 "{%0,%1,%2,%3}, {%4,%5,%6,%7}, {%8,%9}, {%0,%1,%2,%3};" \
                 : "+f"((c)[0]), "+f"((c)[1]), "+f"((c)[2]), "+f"((c)[3]) \
                 : "r"((a)[0]), "r"((a)[1]), "r"((a)[2]), "r"((a)[3]), \
                   "r"(b0), "r"(b1))

// Wt interleaved byte offset: B-fragment {k, k+1, k+8, k+9} contiguous as 8B.
__device__ __forceinline__ int wt_off(int n, int k, int stride) {
    const int kt = k >> 4, kk = k & 15;
    return n * stride + kt * 32 + ((kk & 7) >> 1) * 8 + ((kk >= 8) ? 4 : 0) + (kk & 1) * 2;
}

// ============================================================================
__global__ void __launch_bounds__(256)
prep_w1_kernel(const float* __restrict__ W1)
{
    const int i = blockIdx.x * 256 + threadIdx.x;
    if (i < K1 * D) {
        const int k = i >> 6, n = i & 63;
        *(__nv_bfloat16*)(g_w1img + wt_off(n, k, W1_STRIDE)) = __float2bfloat16(W1[i]);
    }
}

__global__ void __launch_bounds__(256)
prep_w2_kernel(const float* __restrict__ W2)
{
    const int i = blockIdx.x * 256 + threadIdx.x;
    if (i < D * D) {
        const int k = i >> 6, n = i & 63;
        *(__nv_bfloat16*)(g_w2img + wt_off(n, k, W2_STRIDE)) = __float2bfloat16(W2[i]);
    }
}

__global__ void __launch_bounds__(256)
prep_bias_kernel(const float* __restrict__ b1, const float* __restrict__ b2,
                 const float* __restrict__ w3, const float* __restrict__ b3)
{
    const int i = threadIdx.x;
    float v = 0.f;
    if (i < 64)        v = b1[i];
    else if (i < 128)  v = b2[i - 64];
    else if (i < 192)  v = w3[i - 128];
    else if (i == 192) v = b3[0];
    g_bias[i] = v;
}

// ============================================================================
__global__ void __launch_bounds__(THREADS1, 2)
mlp_score_kernel(const int* __restrict__ nodes,
                 const int* __restrict__ hva,
                 const int* __restrict__ haf,
                 const float* __restrict__ v2e,
                 const float* __restrict__ a2e,
                 const float* __restrict__ f2e,
                 int nT32, int nNodes, int nRows)
{
    extern __shared__ char sm[];
    const uint32_t sbase = smem_u32(sm);

    const int tid  = threadIdx.x;
    const int lane = tid & 31;
    const int wid  = tid >> 5;

    float* sBias = (float*)(sm + OFF_BIAS);
    float* sB1 = sBias;
    float* sB2 = sBias + 64;
    float* sW3 = sBias + 128;

    // ---- stage weights once per CTA, then one block sync ----
    {
        const uint4* s1 = (const uint4*)g_w1img;
        const uint4* s2 = (const uint4*)g_w2img;
        uint4* d1 = (uint4*)(sm + OFF_W1);
        uint4* d2 = (uint4*)(sm + OFF_W2);
        #pragma unroll 2
        for (int i = tid; i < W1_BYTES / 16; i += THREADS1) d1[i] = s1[i];
        for (int i = tid; i < W2_BYTES / 16; i += THREADS1) d2[i] = s2[i];
        for (int i = tid; i < 256; i += THREADS1) sBias[i] = g_bias[i];
    }
    __syncthreads();

    const int g  = lane >> 2;
    const int tg = lane & 3;
    const uint32_t aWarp  = sbase + OFF_A + wid * ROWS_W * A_STRIDE;
    const uint32_t aBase0 = aWarp + (lane & 15) * A_STRIDE + (lane >> 4) * 16;
    const uint32_t aBase1 = aBase0 + 16 * A_STRIDE;
    const uint32_t w1Base = sbase + OFF_W1 + g * W1_STRIDE + tg * 8;
    const uint32_t w2Base = sbase + OFF_W2 + g * W2_STRIDE + tg * 8;

    const int gwarp = blockIdx.x * WARPS1 + wid;
    const int totalWarps = GRID1 * WARPS1;
    const float b3v = sBias[192];

    for (int t = gwarp; t < nT32; t += totalWarps) {
        const int r0 = t * ROWS_W;

        // ---- own history indices for all 32 rows ----
        int rr = r0 + lane;
        if (rr > nRows - 1) rr = nRows - 1;
        const int myVa = hva[rr];
        const int myAf = haf[rr];

        // ---- rep: 32 rows span at most 2 nodes (L=50 > 32) ----
        const int node0  = r0 / L;
        const int nbound = (node0 + 1) * L - r0;     // rows [0, nbound) -> node0
        int n1 = node0 + 1; if (n1 > nNodes - 1) n1 = nNodes - 1;
        const int item0 = nodes[node0];
        const int item1 = nodes[n1];
        const float2 rv0 = reinterpret_cast<const float2*>(v2e + (size_t)item0 * D)[lane];
        const float2 rv1 = reinterpret_cast<const float2*>(v2e + (size_t)item1 * D)[lane];
        uint32_t pk0, pk1;
        CVT_BF16X2(pk0, rv0.x, rv0.y);
        CVT_BF16X2(pk1, rv1.x, rv1.y);

        // ---- fill rep segment ----
        #pragma unroll 8
        for (int i = 0; i < ROWS_W; ++i) {
            const uint32_t pk = (i < nbound) ? pk0 : pk1;
            asm volatile("st.shared.b32 [%0], %1;"
                         :: "r"(aWarp + i * A_STRIDE + 128 + lane * 4),
                            "r"(pk) : "memory");
        }

        // ---- gather e_va / e_af rows: 4 batches of 16 LDG.64 in flight ----
        #pragma unroll
        for (int half = 0; half < 2; ++half) {
            {
                float2 v[16];
                #pragma unroll
                for (int u = 0; u < 16; ++u) {
                    const int idx = __shfl_sync(0xffffffffu, myVa, half * 16 + u);
                    v[u] = reinterpret_cast<const float2*>(a2e + (size_t)idx * D)[lane];
                }
                #pragma unroll
                for (int u = 0; u < 16; ++u) {
                    uint32_t pk;
                    CVT_BF16X2(pk, v[u].x, v[u].y);
                    asm volatile("st.shared.b32 [%0], %1;"
                        :: "r"(aWarp + (half * 16 + u) * A_STRIDE + lane * 4),
                           "r"(pk) : "memory");
                }
            }
            {
                float2 v[16];
                #pragma unroll
                for (int u = 0; u < 16; ++u) {
                    const int idx = __shfl_sync(0xffffffffu, myAf, half * 16 + u);
                    v[u] = reinterpret_cast<const float2*>(f2e + (size_t)idx * D)[lane];
                }
                #pragma unroll
                for (int u = 0; u < 16; ++u) {
                    uint32_t pk;
                    CVT_BF16X2(pk, v[u].x, v[u].y);
                    asm volatile("st.shared.b32 [%0], %1;"
                        :: "r"(aWarp + (half * 16 + u) * A_STRIDE + 256 + lane * 4),
                           "r"(pk) : "memory");
                }
            }
        }
        __syncwarp();

        // ---- layer 1: two [16x192]@[192x64] sub-tiles sharing B fragments ----
        float acc[2][8][4];
        #pragma unroll
        for (int s = 0; s < 2; ++s)
            #pragma unroll
            for (int j = 0; j < 8; ++j)
                #pragma unroll
                for (int q = 0; q < 4; ++q) acc[s][j][q] = 0.f;

        #pragma unroll
        for (int kt = 0; kt < 12; ++kt) {
            uint32_t a0[4], a1[4];
            LDSM_X4(a0[0], a0[1], a0[2], a0[3], aBase0 + kt * 32);
            LDSM_X4(a1[0], a1[1], a1[2], a1[3], aBase1 + kt * 32);
            #pragma unroll
            for (int j = 0; j < 8; ++j) {
                uint32_t b0v, b1v;
                LDS_V2(b0v, b1v, w1Base + j * 8 * W1_STRIDE + kt * 32);
                MMA_16816(acc[0][j], a0, b0v, b1v);
                MMA_16816(acc[1][j], a1, b0v, b1v);
            }
        }

        // ---- epilogue 1: bias + relu + repack C -> A fragments ----
        uint32_t a2[2][4][4];
        #pragma unroll
        for (int s = 0; s < 2; ++s)
            #pragma unroll
            for (int j = 0; j < 8; ++j) {
                const float2 bb = *(const float2*)(sB1 + j * 8 + tg * 2);
                const float h0 = fmaxf(acc[s][j][0] + bb.x, 0.f);
                const float h1 = fmaxf(acc[s][j][1] + bb.y, 0.f);
                const float h2 = fmaxf(acc[s][j][2] + bb.x, 0.f);
                const float h3 = fmaxf(acc[s][j][3] + bb.y, 0.f);
                CVT_BF16X2(a2[s][j >> 1][(j & 1) * 2 + 0], h0, h1);
                CVT_BF16X2(a2[s][j >> 1][(j & 1) * 2 + 1], h2, h3);
            }

        // ---- layer 2: two [16x64]@[64x64] sub-tiles sharing B fragments ----
        float acc2[2][8][4];
        #pragma unroll
        for (int s = 0; s < 2; ++s)
            #pragma unroll
            for (int j = 0; j < 8; ++j)
                #pragma unroll
                for (int q = 0; q < 4; ++q) acc2[s][j][q] = 0.f;

        #pragma unroll
        for (int kt = 0; kt < 4; ++kt) {
            #pragma unroll
            for (int j = 0; j < 8; ++j) {
                uint32_t b0v, b1v;
                LDS_V2(b0v, b1v, w2Base + j * 8 * W2_STRIDE + kt * 32);
                MMA_16816(acc2[0][j], a2[0][kt], b0v, b1v);
                MMA_16816(acc2[1][j], a2[1][kt], b0v, b1v);
            }
        }

        // ---- epilogue 2: bias + relu + dot(w3), group-of-4 reduce ----
        #pragma unroll
        for (int s = 0; s < 2; ++s) {
            float plo = 0.f, phi = 0.f;
            #pragma unroll
            for (int j = 0; j < 8; ++j) {
                const int col = j * 8 + tg * 2;
                const float2 bb = *(const float2*)(sB2 + col);
                const float2 ww = *(const float2*)(sW3 + col);
                const float v0 = fmaxf(acc2[s][j][0] + bb.x, 0.f);
                const float v1 = fmaxf(acc2[s][j][1] + bb.y, 0.f);
                const float v2 = fmaxf(acc2[s][j][2] + bb.x, 0.f);
                const float v3 = fmaxf(acc2[s][j][3] + bb.y, 0.f);
                plo = fmaf(v0, ww.x, fmaf(v1, ww.y, plo));
                phi = fmaf(v2, ww.x, fmaf(v3, ww.y, phi));
            }
            #pragma unroll
            for (int o = 1; o <= 2; o <<= 1) {
                plo += __shfl_xor_sync(0xffffffffu, plo, o);
                phi += __shfl_xor_sync(0xffffffffu, phi, o);
            }
            if (tg == 0) {
                const int gr = r0 + s * 16 + g;
                if (gr < nRows)     g_scores[gr]     = plo + b3v;
                if (gr + 8 < nRows) g_scores[gr + 8] = phi + b3v;
            }
        }
        __syncwarp();   // A slab reuse in next iteration
    }
}

// ============================================================================
__global__ void __launch_bounds__(256)
softmax_agg_kernel(const int* __restrict__ hva,
                   const float* __restrict__ a2e,
                   float* __restrict__ out, int nNodes)
{
    __shared__ float sAtt[8][52];
    __shared__ int   sIdx[8][52];
    const int lane = threadIdx.x & 31;
    const int wid  = threadIdx.x >> 5;
    const int n = blockIdx.x * 8 + wid;
    if (n >= nNodes) return;

    const float s1 = g_scores[n * L + lane];
    const bool has2 = lane < (L - 32);
    const float s2 = has2 ? g_scores[n * L + 32 + lane] : -1e30f;
    sIdx[wid][lane] = hva[n * L + lane];
    if (has2) sIdx[wid][32 + lane] = hva[n * L + 32 + lane];

    float m = fmaxf(s1, s2);
    #pragma unroll
    for (int o = 16; o > 0; o >>= 1)
        m = fmaxf(m, __shfl_xor_sync(0xffffffffu, m, o));
    const float e1 = __expf(s1 - m);
    const float e2 = has2 ? __expf(s2 - m) : 0.f;
    float ss = e1 + e2;
    #pragma unroll
    for (int o = 16; o > 0; o >>= 1)
        ss += __shfl_xor_sync(0xffffffffu, ss, o);
    const float inv = 1.f / ss;
    sAtt[wid][lane] = e1 * inv;
    if (has2) sAtt[wid][32 + lane] = e2 * inv;
    __syncwarp();

    float oa = 0.f, ob = 0.f;
    #pragma unroll 10
    for (int l = 0; l < L; ++l) {
        const float2 v =
            reinterpret_cast<const float2*>(a2e + (size_t)sIdx[wid][l] * D)[lane];
        const float att = sAtt[wid][l];
        oa = fmaf(att, v.x, oa);
        ob = fmaf(att, v.y, ob);
    }
    reinterpret_cast<float2*>(out + (size_t)n * D)[lane] = make_float2(oa, ob);
}

// ============================================================================
extern "C" void kernel_launch(void* const* d_in, const int* in_sizes, int n_in,
                              void* d_out, int out_size)
{
    const int*   nodes = (const int*)  d_in[0];
    const int*   hva   = (const int*)  d_in[1];
    const int*   haf   = (const int*)  d_in[2];
    const float* v2e   = (const float*)d_in[3];
    const float* a2e   = (const float*)d_in[4];
    const float* f2e   = (const float*)d_in[5];
    const float* W1    = (const float*)d_in[6];
    const float* b1    = (const float*)d_in[7];
    const float* W2    = (const float*)d_in[8];
    const float* b2    = (const float*)d_in[9];
    const float* w3    = (const float*)d_in[10];
    const float* b3    = (const float*)d_in[11];
    float* out = (float*)d_out;

    const int nNodes = in_sizes[0];
    const int nRows  = nNodes * L;
    const int nT32   = (nRows + ROWS_W - 1) / ROWS_W;
    const int grid2  = (nNodes + 7) / 8;

    cudaFuncSetAttribute(mlp_score_kernel,
                         cudaFuncAttributeMaxDynamicSharedMemorySize, SMEM_BYTES);

    // mlp_score_kernel stays at global launch #4 (= the ncu capture window).
    prep_w1_kernel<<<(K1 * D + 255) / 256, 256>>>(W1);
    prep_w2_kernel<<<(D * D + 255) / 256, 256>>>(W2);
    prep_bias_kernel<<<1, 256>>>(b1, b2, w3, b3);
    mlp_score_kernel<<<GRID1, THREADS1, SMEM_BYTES>>>(
        nodes, hva, haf, v2e, a2e, f2e, nT32, nNodes, nRows);
    softmax_agg_kernel<<<grid2, 256>>>(hva, a2e, out, nNodes);
}

// round 9
// speedup vs baseline: 1.1688x; 1.1688x over previous
#include <cuda_runtime.h>
#include <cuda_bf16.h>
#include <cstdint>

// ============================================================================
// VA_Aggregator via mma.sync bf16 HMMA (sm_103 baseline PTX; no tcgen05).
// K0a/b/c: pre-convert W1/W2 -> bf16 interleaved SMEM-images, pack biases.
// K1 (persistent, warp-autonomous, SOFTWARE-PIPELINED): each warp owns a
//     16-row tile; while doing HMMA on tile t it prefetches tile t+1's
//     gather (LDG.64 x16 per segment) into registers, STSing them into the
//     slab between MMA phases. 8 warps/CTA, 2 CTA/SM (reg-capped at 128).
// K2: per-node softmax over L=50 + fp32 weighted gather of e_va (LDG.64).
// ============================================================================

constexpr int L      = 50;
constexpr int D      = 64;
constexpr int K1     = 192;
constexpr int NMAX_ROWS = 8192 * 50;
constexpr int GRID1  = 296;
constexpr int WARPS1 = 8;

__device__ float g_scores[NMAX_ROWS];
__device__ float g_bias[256];                  // [0:64)=b1 [64:128)=b2 [128:192)=w3 [192]=b3

// ---- SMEM layout (bytes from dynamic smem base) ----
constexpr int A_STRIDE  = 400;                 // 192*2 + 16 pad (ldsm conflict-free)
constexpr int W1_STRIDE = 416;                 // 104 words ≡ 8 mod 32
constexpr int W2_STRIDE = 160;                 // 40 words  ≡ 8 mod 32
constexpr int W1_BYTES  = 64 * W1_STRIDE;      // 26624
constexpr int W2_BYTES  = 64 * W2_STRIDE;      // 10240
constexpr int OFF_A    = 0;                    // 128 * 400 = 51200
constexpr int OFF_W1   = 51200;
constexpr int OFF_W2   = 77824;
constexpr int OFF_BIAS = 88064;                // 256 f
constexpr int SMEM_BYTES = 89088 + 32;

__device__ __align__(16) uint8_t g_w1img[W1_BYTES];
__device__ __align__(16) uint8_t g_w2img[W2_BYTES];

__device__ __forceinline__ uint32_t smem_u32(const void* p) {
    uint32_t a;
    asm("{ .reg .u64 t; cvta.to.shared.u64 t, %1; cvt.u32.u64 %0, t; }"
        : "=r"(a) : "l"(p));
    return a;
}

#define CVT_BF16X2(res, lo, hi) \
    asm("cvt.rn.satfinite.bf16x2.f32 %0, %1, %2;" : "=r"(res) : "f"(hi), "f"(lo))

#define LDSM_X4(r0, r1, r2, r3, addr) \
    asm volatile("ldmatrix.sync.aligned.m8n8.x4.shared.b16 {%0,%1,%2,%3}, [%4];" \
                 : "=r"(r0), "=r"(r1), "=r"(r2), "=r"(r3) : "r"(addr))

#define LDS_V2(r0, r1, addr) \
    asm volatile("ld.shared.v2.u32 {%0,%1}, [%2];" \
                 : "=r"(r0), "=r"(r1) : "r"(addr))

#define STS_B32(addr, val) \
    asm volatile("st.shared.b32 [%0], %1;" :: "r"(addr), "r"(val) : "memory")

#define MMA_16816(c, a, b0, b1) \
    asm volatile("mma.sync.aligned.m16n8k16.row.col.f32.bf16.bf16.f32 " \
                 "{%0,%1,%2,%3}, {%4,%5,%6,%7}, {%8,%9}, {%0,%1,%2,%3};" \
                 : "+f"((c)[0]), "+f"((c)[1]), "+f"((c)[2]), "+f"((c)[3]) \
                 : "r"((a)[0]), "r"((a)[1]), "r"((a)[2]), "r"((a)[3]), \
                   "r"(b0), "r"(b1))

// Wt interleaved byte offset: B-fragment {k, k+1, k+8, k+9} contiguous as 8B.
__device__ __forceinline__ int wt_off(int n, int k, int stride) {
    const int kt = k >> 4, kk = k & 15;
    return n * stride + kt * 32 + ((kk & 7) >> 1) * 8 + ((kk >= 8) ? 4 : 0) + (kk & 1) * 2;
}

// ============================================================================
__global__ void __launch_bounds__(256)
prep_w1_kernel(const float* __restrict__ W1)
{
    const int i = blockIdx.x * 256 + threadIdx.x;
    if (i < K1 * D) {
        const int k = i >> 6, n = i & 63;
        *(__nv_bfloat16*)(g_w1img + wt_off(n, k, W1_STRIDE)) = __float2bfloat16(W1[i]);
    }
}

__global__ void __launch_bounds__(256)
prep_w2_kernel(const float* __restrict__ W2)
{
    const int i = blockIdx.x * 256 + threadIdx.x;
    if (i < D * D) {
        const int k = i >> 6, n = i & 63;
        *(__nv_bfloat16*)(g_w2img + wt_off(n, k, W2_STRIDE)) = __float2bfloat16(W2[i]);
    }
}

__global__ void __launch_bounds__(256)
prep_bias_kernel(const float* __restrict__ b1, const float* __restrict__ b2,
                 const float* __restrict__ w3, const float* __restrict__ b3)
{
    const int i = threadIdx.x;
    float v = 0.f;
    if (i < 64)        v = b1[i];
    else if (i < 128)  v = b2[i - 64];
    else if (i < 192)  v = w3[i - 128];
    else if (i == 192) v = b3[0];
    g_bias[i] = v;
}

// ============================================================================
__global__ void __launch_bounds__(32 * WARPS1, 2)
mlp_score_kernel(const int* __restrict__ nodes,
                 const int* __restrict__ hva,
                 const int* __restrict__ haf,
                 const float* __restrict__ v2e,
                 const float* __restrict__ a2e,
                 const float* __restrict__ f2e,
                 int nT16, int nNodes, int nRows)
{
    extern __shared__ char sm[];
    const uint32_t sbase = smem_u32(sm);

    const int tid  = threadIdx.x;
    const int lane = tid & 31;
    const int wid  = tid >> 5;

    float* sBias = (float*)(sm + OFF_BIAS);
    float* sB1 = sBias;
    float* sB2 = sBias + 64;
    float* sW3 = sBias + 128;

    // ---- stage weights once per CTA, then one block sync ----
    {
        const uint4* s1 = (const uint4*)g_w1img;
        const uint4* s2 = (const uint4*)g_w2img;
        uint4* d1 = (uint4*)(sm + OFF_W1);
        uint4* d2 = (uint4*)(sm + OFF_W2);
        #pragma unroll 2
        for (int i = tid; i < W1_BYTES / 16; i += 32 * WARPS1) d1[i] = s1[i];
        for (int i = tid; i < W2_BYTES / 16; i += 32 * WARPS1) d2[i] = s2[i];
        sBias[tid] = g_bias[tid];
    }
    __syncthreads();

    const int g  = lane >> 2;
    const int tg = lane & 3;
    const uint32_t aWarp  = sbase + OFF_A + wid * 16 * A_STRIDE;
    const uint32_t aBase  = aWarp + (lane & 15) * A_STRIDE + (lane >> 4) * 16;
    const uint32_t w1Base = sbase + OFF_W1 + g * W1_STRIDE + tg * 8;
    const uint32_t w2Base = sbase + OFF_W2 + g * W2_STRIDE + tg * 8;

    const int gwarp = blockIdx.x * WARPS1 + wid;
    const int totalWarps = GRID1 * WARPS1;
    const float b3v = sBias[192];

    int t = gwarp;
    if (t >= nT16) return;

    // ---- prologue: fill slab for the first tile ----
    {
        const int r0 = t * 16;
        int rr = r0 + (lane & 15);
        if (rr > nRows - 1) rr = nRows - 1;
        const int myIdx = (lane < 16) ? hva[rr] : haf[rr];
        const int node0  = r0 / L;
        const int nbound = (node0 + 1) * L - r0;
        int n1 = node0 + 1; if (n1 > nNodes - 1) n1 = nNodes - 1;
        const float2 rv0 = ((const float2*)(v2e + (size_t)nodes[node0] * D))[lane];
        const float2 rv1 = ((const float2*)(v2e + (size_t)nodes[n1] * D))[lane];
        uint32_t pk0, pk1;
        CVT_BF16X2(pk0, rv0.x, rv0.y);
        CVT_BF16X2(pk1, rv1.x, rv1.y);
        #pragma unroll 4
        for (int i = 0; i < 16; ++i)
            STS_B32(aWarp + i * A_STRIDE + 128 + lane * 4, (i < nbound) ? pk0 : pk1);
        float2 v[16];
        #pragma unroll
        for (int u = 0; u < 16; ++u) {
            const int idx = __shfl_sync(0xffffffffu, myIdx, u);
            v[u] = ((const float2*)(a2e + (size_t)idx * D))[lane];
        }
        #pragma unroll
        for (int u = 0; u < 16; ++u) {
            uint32_t pk; CVT_BF16X2(pk, v[u].x, v[u].y);
            STS_B32(aWarp + u * A_STRIDE + lane * 4, pk);
        }
        #pragma unroll
        for (int u = 0; u < 16; ++u) {
            const int idx = __shfl_sync(0xffffffffu, myIdx, u + 16);
            v[u] = ((const float2*)(f2e + (size_t)idx * D))[lane];
        }
        #pragma unroll
        for (int u = 0; u < 16; ++u) {
            uint32_t pk; CVT_BF16X2(pk, v[u].x, v[u].y);
            STS_B32(aWarp + u * A_STRIDE + 256 + lane * 4, pk);
        }
        __syncwarp();
    }

    // ---- pipelined main loop: MMA on tile t, prefetch tile t+stride ----
    for (; t < nT16; t += totalWarps) {
        const int r0 = t * 16;
        const int tn = t + totalWarps;
        const int tN = (tn < nT16) ? tn : t;    // last iter: harmless re-gather
        const int r0n = tN * 16;

        // -- next-tile metadata + rep regs --
        int rrN = r0n + (lane & 15);
        if (rrN > nRows - 1) rrN = nRows - 1;
        const int myIdxN = (lane < 16) ? hva[rrN] : haf[rrN];
        const int node0N  = r0n / L;
        const int nboundN = (node0N + 1) * L - r0n;
        int n1N = node0N + 1; if (n1N > nNodes - 1) n1N = nNodes - 1;
        const float2 rv0 = ((const float2*)(v2e + (size_t)nodes[node0N] * D))[lane];
        const float2 rv1 = ((const float2*)(v2e + (size_t)nodes[n1N]   * D))[lane];

        // -- issue next-tile va gather (lands during layer-1 MMA) --
        float2 vva[16];
        #pragma unroll
        for (int u = 0; u < 16; ++u) {
            const int idx = __shfl_sync(0xffffffffu, myIdxN, u);
            vva[u] = ((const float2*)(a2e + (size_t)idx * D))[lane];
        }

        // ---- layer 1: [16x192] @ [192x64] ----
        float acc[8][4];
        #pragma unroll
        for (int j = 0; j < 8; ++j)
            #pragma unroll
            for (int q = 0; q < 4; ++q) acc[j][q] = 0.f;

        #pragma unroll
        for (int kt = 0; kt < 12; ++kt) {
            uint32_t a[4];
            LDSM_X4(a[0], a[1], a[2], a[3], aBase + kt * 32);
            #pragma unroll
            for (int j = 0; j < 8; ++j) {
                uint32_t b0v, b1v;
                LDS_V2(b0v, b1v, w1Base + j * 8 * W1_STRIDE + kt * 32);
                MMA_16816(acc[j], a, b0v, b1v);
            }
        }

        // ---- epilogue 1: bias + relu + repack C -> A fragments ----
        uint32_t a2[4][4];
        #pragma unroll
        for (int j = 0; j < 8; ++j) {
            const float2 bb = *(const float2*)(sB1 + j * 8 + tg * 2);
            const float h0 = fmaxf(acc[j][0] + bb.x, 0.f);
            const float h1 = fmaxf(acc[j][1] + bb.y, 0.f);
            const float h2 = fmaxf(acc[j][2] + bb.x, 0.f);
            const float h3 = fmaxf(acc[j][3] + bb.y, 0.f);
            CVT_BF16X2(a2[j >> 1][(j & 1) * 2 + 0], h0, h1);
            CVT_BF16X2(a2[j >> 1][(j & 1) * 2 + 1], h2, h3);
        }

        // -- slab va segment no longer read: commit prefetched va, issue af --
        #pragma unroll
        for (int u = 0; u < 16; ++u) {
            uint32_t pk; CVT_BF16X2(pk, vva[u].x, vva[u].y);
            STS_B32(aWarp + u * A_STRIDE + lane * 4, pk);
        }
        float2 vaf[16];
        #pragma unroll
        for (int u = 0; u < 16; ++u) {
            const int idx = __shfl_sync(0xffffffffu, myIdxN, u + 16);
            vaf[u] = ((const float2*)(f2e + (size_t)idx * D))[lane];
        }

        // ---- layer 2: [16x64] @ [64x64] (A from registers) ----
        float acc2[8][4];
        #pragma unroll
        for (int j = 0; j < 8; ++j)
            #pragma unroll
            for (int q = 0; q < 4; ++q) acc2[j][q] = 0.f;

        #pragma unroll
        for (int kt = 0; kt < 4; ++kt) {
            #pragma unroll
            for (int j = 0; j < 8; ++j) {
                uint32_t b0v, b1v;
                LDS_V2(b0v, b1v, w2Base + j * 8 * W2_STRIDE + kt * 32);
                MMA_16816(acc2[j], a2[kt], b0v, b1v);
            }
        }

        // -- commit prefetched af + rep for next tile --
        #pragma unroll
        for (int u = 0; u < 16; ++u) {
            uint32_t pk; CVT_BF16X2(pk, vaf[u].x, vaf[u].y);
            STS_B32(aWarp + u * A_STRIDE + 256 + lane * 4, pk);
        }
        {
            uint32_t pk0, pk1;
            CVT_BF16X2(pk0, rv0.x, rv0.y);
            CVT_BF16X2(pk1, rv1.x, rv1.y);
            #pragma unroll 4
            for (int i = 0; i < 16; ++i)
                STS_B32(aWarp + i * A_STRIDE + 128 + lane * 4,
                        (i < nboundN) ? pk0 : pk1);
        }

        // ---- epilogue 2: bias + relu + dot(w3), group-of-4 reduce ----
        float plo = 0.f, phi = 0.f;
        #pragma unroll
        for (int j = 0; j < 8; ++j) {
            const int col = j * 8 + tg * 2;
            const float2 bb = *(const float2*)(sB2 + col);
            const float2 ww = *(const float2*)(sW3 + col);
            const float v0 = fmaxf(acc2[j][0] + bb.x, 0.f);
            const float v1 = fmaxf(acc2[j][1] + bb.y, 0.f);
            const float v2 = fmaxf(acc2[j][2] + bb.x, 0.f);
            const float v3 = fmaxf(acc2[j][3] + bb.y, 0.f);
            plo = fmaf(v0, ww.x, fmaf(v1, ww.y, plo));
            phi = fmaf(v2, ww.x, fmaf(v3, ww.y, phi));
        }
        #pragma unroll
        for (int o = 1; o <= 2; o <<= 1) {
            plo += __shfl_xor_sync(0xffffffffu, plo, o);
            phi += __shfl_xor_sync(0xffffffffu, phi, o);
        }
        if (tg == 0) {
            const int gr = r0 + g;
            if (gr < nRows)     g_scores[gr]     = plo + b3v;
            if (gr + 8 < nRows) g_scores[gr + 8] = phi + b3v;
        }
        __syncwarp();
    }
}

// ============================================================================
__global__ void __launch_bounds__(256)
softmax_agg_kernel(const int* __restrict__ hva,
                   const float* __restrict__ a2e,
                   float* __restrict__ out, int nNodes)
{
    __shared__ float sAtt[8][52];
    __shared__ int   sIdx[8][52];
    const int lane = threadIdx.x & 31;
    const int wid  = threadIdx.x >> 5;
    const int n = blockIdx.x * 8 + wid;
    if (n >= nNodes) return;

    const float s1 = g_scores[n * L + lane];
    const bool has2 = lane < (L - 32);
    const float s2 = has2 ? g_scores[n * L + 32 + lane] : -1e30f;
    sIdx[wid][lane] = hva[n * L + lane];
    if (has2) sIdx[wid][32 + lane] = hva[n * L + 32 + lane];

    float m = fmaxf(s1, s2);
    #pragma unroll
    for (int o = 16; o > 0; o >>= 1)
        m = fmaxf(m, __shfl_xor_sync(0xffffffffu, m, o));
    const float e1 = __expf(s1 - m);
    const float e2 = has2 ? __expf(s2 - m) : 0.f;
    float ss = e1 + e2;
    #pragma unroll
    for (int o = 16; o > 0; o >>= 1)
        ss += __shfl_xor_sync(0xffffffffu, ss, o);
    const float inv = 1.f / ss;
    sAtt[wid][lane] = e1 * inv;
    if (has2) sAtt[wid][32 + lane] = e2 * inv;
    __syncwarp();

    float oa = 0.f, ob = 0.f;
    #pragma unroll 10
    for (int l = 0; l < L; ++l) {
        const float2 v =
            reinterpret_cast<const float2*>(a2e + (size_t)sIdx[wid][l] * D)[lane];
        const float att = sAtt[wid][l];
        oa = fmaf(att, v.x, oa);
        ob = fmaf(att, v.y, ob);
    }
    reinterpret_cast<float2*>(out + (size_t)n * D)[lane] = make_float2(oa, ob);
}

// ============================================================================
extern "C" void kernel_launch(void* const* d_in, const int* in_sizes, int n_in,
                              void* d_out, int out_size)
{
    const int*   nodes = (const int*)  d_in[0];
    const int*   hva   = (const int*)  d_in[1];
    const int*   haf   = (const int*)  d_in[2];
    const float* v2e   = (const float*)d_in[3];
    const float* a2e   = (const float*)d_in[4];
    const float* f2e   = (const float*)d_in[5];
    const float* W1    = (const float*)d_in[6];
    const float* b1    = (const float*)d_in[7];
    const float* W2    = (const float*)d_in[8];
    const float* b2    = (const float*)d_in[9];
    const float* w3    = (const float*)d_in[10];
    const float* b3    = (const float*)d_in[11];
    float* out = (float*)d_out;

    const int nNodes = in_sizes[0];
    const int nRows  = nNodes * L;
    const int nT16   = (nRows + 15) / 16;
    const int grid2  = (nNodes + 7) / 8;

    cudaFuncSetAttribute(mlp_score_kernel,
                         cudaFuncAttributeMaxDynamicSharedMemorySize, SMEM_BYTES);

    // mlp_score_kernel stays at global launch #4 (= the ncu capture window).
    prep_w1_kernel<<<(K1 * D + 255) / 256, 256>>>(W1);
    prep_w2_kernel<<<(D * D + 255) / 256, 256>>>(W2);
    prep_bias_kernel<<<1, 256>>>(b1, b2, w3, b3);
    mlp_score_kernel<<<GRID1, 32 * WARPS1, SMEM_BYTES>>>(
        nodes, hva, haf, v2e, a2e, f2e, nT16, nNodes, nRows);
    softmax_agg_kernel<<<grid2, 256>>>(hva, a2e, out, nNodes);
}

// round 10
// speedup vs baseline: 1.1894x; 1.0176x over previous
#include <cuda_runtime.h>
#include <cuda_bf16.h>
#include <cstdint>

// ============================================================================
// VA_Aggregator via mma.sync bf16 HMMA (sm_103 baseline PTX; no tcgen05).
// K0a/b/c: pre-convert W1/W2 -> bf16 interleaved SMEM-images, pack biases.
// K1 (persistent, warp-autonomous): ONE 12-warp CTA per SM (191.5 KB SMEM),
//     32 rows per warp (two 16-row MMA sub-tiles sharing each weight-fragment
//     LDS). Combines R8's LDS-byte halving with near-R7 warp count.
// K2: per-node softmax over L=50 + fp32 weighted gather of e_va (LDG.64).
// ============================================================================

constexpr int L      = 50;
constexpr int D      = 64;
constexpr int K1     = 192;
constexpr int NMAX_ROWS = 8192 * 50;
constexpr int GRID1   = 148;                   // 1 CTA per SM
constexpr int WARPS1  = 12;
constexpr int THREADS1 = 32 * WARPS1;          // 384
constexpr int ROWS_W  = 32;                    // rows per warp tile

__device__ float g_scores[NMAX_ROWS];
__device__ float g_bias[256];                  // [0:64)=b1 [64:128)=b2 [128:192)=w3 [192]=b3

// ---- SMEM layout (bytes from dynamic smem base) ----
constexpr int A_STRIDE  = 400;                 // 192*2 + 16 pad (ldsm conflict-free)
constexpr int W1_STRIDE = 416;                 // 104 words ≡ 8 mod 32 (conflict-free)
constexpr int W2_STRIDE = 160;                 // 40 words  ≡ 8 mod 32
constexpr int W1_BYTES  = 64 * W1_STRIDE;      // 26624
constexpr int W2_BYTES  = 64 * W2_STRIDE;      // 10240
constexpr int A_BYTES   = WARPS1 * ROWS_W * A_STRIDE;   // 153600
constexpr int OFF_A    = 0;
constexpr int OFF_W1   = A_BYTES;                        // 153600
constexpr int OFF_W2   = OFF_W1 + W1_BYTES;              // 180224
constexpr int OFF_BIAS = OFF_W2 + W2_BYTES;              // 190464
constexpr int SMEM_BYTES = OFF_BIAS + 1024 + 32;         // ~191520

__device__ __align__(16) uint8_t g_w1img[W1_BYTES];
__device__ __align__(16) uint8_t g_w2img[W2_BYTES];

__device__ __forceinline__ uint32_t smem_u32(const void* p) {
    uint32_t a;
    asm("{ .reg .u64 t; cvta.to.shared.u64 t, %1; cvt.u32.u64 %0, t; }"
        : "=r"(a) : "l"(p));
    return a;
}

#define CVT_BF16X2(res, lo, hi) \
    asm("cvt.rn.satfinite.bf16x2.f32 %0, %1, %2;" : "=r"(res) : "f"(hi), "f"(lo))

#define LDSM_X4(r0, r1, r2, r3, addr) \
    asm volatile("ldmatrix.sync.aligned.m8n8.x4.shared.b16 {%0,%1,%2,%3}, [%4];" \
                 : "=r"(r0), "=r"(r1), "=r"(r2), "=r"(r3) : "r"(addr))

#define LDS_V2(r0, r1, addr) \
    asm volatile("ld.shared.v2.u32 {%0,%1}, [%2];" \
                 : "=r"(r0), "=r"(r1) : "r"(addr))

#define STS_B32(addr, val) \
    asm volatile("st.shared.b32 [%0], %1;" :: "r"(addr), "r"(val) : "memory")

#define MMA_16816(c, a, b0, b1) \
    asm volatile("mma.sync.aligned.m16n8k16.row.col.f32.bf16.bf16.f32 " \
                 "{%0,%1,%2,%3}, {%4,%5,%6,%7}, {%8,%9}, {%0,%1,%2,%3};" \
                 : "+f"((c)[0]), "+f"((c)[1]), "+f"((c)[2]), "+f"((c)[3]) \
                 : "r"((a)[0]), "r"((a)[1]), "r"((a)[2]), "r"((a)[3]), \
                   "r"(b0), "r"(b1))

// Wt interleaved byte offset: B-fragment {k, k+1, k+8, k+9} contiguous as 8B.
__device__ __forceinline__ int wt_off(int n, int k, int stride) {
    const int kt = k >> 4, kk = k & 15;
    return n * stride + kt * 32 + ((kk & 7) >> 1) * 8 + ((kk >= 8) ? 4 : 0) + (kk & 1) * 2;
}

// ============================================================================
__global__ void __launch_bounds__(256)
prep_w1_kernel(const float* __restrict__ W1)
{
    const int i = blockIdx.x * 256 + threadIdx.x;
    if (i < K1 * D) {
        const int k = i >> 6, n = i & 63;
        *(__nv_bfloat16*)(g_w1img + wt_off(n, k, W1_STRIDE)) = __float2bfloat16(W1[i]);
    }
}

__global__ void __launch_bounds__(256)
prep_w2_kernel(const float* __restrict__ W2)
{
    const int i = blockIdx.x * 256 + threadIdx.x;
    if (i < D * D) {
        const int k = i >> 6, n = i & 63;
        *(__nv_bfloat16*)(g_w2img + wt_off(n, k, W2_STRIDE)) = __float2bfloat16(W2[i]);
    }
}

__global__ void __launch_bounds__(256)
prep_bias_kernel(const float* __restrict__ b1, const float* __restrict__ b2,
                 const float* __restrict__ w3, const float* __restrict__ b3)
{
    const int i = threadIdx.x;
    float v = 0.f;
    if (i < 64)        v = b1[i];
    else if (i < 128)  v = b2[i - 64];
    else if (i < 192)  v = w3[i - 128];
    else if (i == 192) v = b3[0];
    g_bias[i] = v;
}

// ============================================================================
__global__ void __launch_bounds__(THREADS1, 1)
mlp_score_kernel(const int* __restrict__ nodes,
                 const int* __restrict__ hva,
                 const int* __restrict__ haf,
                 const float* __restrict__ v2e,
                 const float* __restrict__ a2e,
                 const float* __restrict__ f2e,
                 int nT32, int nNodes, int nRows)
{
    extern __shared__ char sm[];
    const uint32_t sbase = smem_u32(sm);

    const int tid  = threadIdx.x;
    const int lane = tid & 31;
    const int wid  = tid >> 5;

    float* sBias = (float*)(sm + OFF_BIAS);
    float* sB1 = sBias;
    float* sB2 = sBias + 64;
    float* sW3 = sBias + 128;

    // ---- stage weights once per SM, then one block sync ----
    {
        const uint4* s1 = (const uint4*)g_w1img;
        const uint4* s2 = (const uint4*)g_w2img;
        uint4* d1 = (uint4*)(sm + OFF_W1);
        uint4* d2 = (uint4*)(sm + OFF_W2);
        #pragma unroll 2
        for (int i = tid; i < W1_BYTES / 16; i += THREADS1) d1[i] = s1[i];
        for (int i = tid; i < W2_BYTES / 16; i += THREADS1) d2[i] = s2[i];
        if (tid < 256) sBias[tid] = g_bias[tid];
    }
    __syncthreads();

    const int g  = lane >> 2;
    const int tg = lane & 3;
    const uint32_t aWarp  = sbase + OFF_A + wid * ROWS_W * A_STRIDE;
    const uint32_t aBase0 = aWarp + (lane & 15) * A_STRIDE + (lane >> 4) * 16;
    const uint32_t aBase1 = aBase0 + 16 * A_STRIDE;
    const uint32_t w1Base = sbase + OFF_W1 + g * W1_STRIDE + tg * 8;
    const uint32_t w2Base = sbase + OFF_W2 + g * W2_STRIDE + tg * 8;

    const int gwarp = blockIdx.x * WARPS1 + wid;
    const int totalWarps = GRID1 * WARPS1;
    const float b3v = sBias[192];

    for (int t = gwarp; t < nT32; t += totalWarps) {
        const int r0 = t * ROWS_W;

        // ---- own history indices for all 32 rows ----
        int rr = r0 + lane;
        if (rr > nRows - 1) rr = nRows - 1;
        const int myVa = hva[rr];
        const int myAf = haf[rr];

        // ---- rep: 32 rows span at most 2 nodes (L=50 > 32) ----
        const int node0  = r0 / L;
        const int nbound = (node0 + 1) * L - r0;     // rows [0, nbound) -> node0
        int n1 = node0 + 1; if (n1 > nNodes - 1) n1 = nNodes - 1;
        const float2 rv0 = ((const float2*)(v2e + (size_t)nodes[node0] * D))[lane];
        const float2 rv1 = ((const float2*)(v2e + (size_t)nodes[n1]   * D))[lane];
        uint32_t pk0, pk1;
        CVT_BF16X2(pk0, rv0.x, rv0.y);
        CVT_BF16X2(pk1, rv1.x, rv1.y);

        // ---- fill rep segment ----
        #pragma unroll 8
        for (int i = 0; i < ROWS_W; ++i)
            STS_B32(aWarp + i * A_STRIDE + 128 + lane * 4, (i < nbound) ? pk0 : pk1);

        // ---- gather e_va / e_af rows: 4 batches of 16 LDG.64 in flight ----
        #pragma unroll
        for (int half = 0; half < 2; ++half) {
            {
                float2 v[16];
                #pragma unroll
                for (int u = 0; u < 16; ++u) {
                    const int idx = __shfl_sync(0xffffffffu, myVa, half * 16 + u);
                    v[u] = ((const float2*)(a2e + (size_t)idx * D))[lane];
                }
                #pragma unroll
                for (int u = 0; u < 16; ++u) {
                    uint32_t pk; CVT_BF16X2(pk, v[u].x, v[u].y);
                    STS_B32(aWarp + (half * 16 + u) * A_STRIDE + lane * 4, pk);
                }
            }
            {
                float2 v[16];
                #pragma unroll
                for (int u = 0; u < 16; ++u) {
                    const int idx = __shfl_sync(0xffffffffu, myAf, half * 16 + u);
                    v[u] = ((const float2*)(f2e + (size_t)idx * D))[lane];
                }
                #pragma unroll
                for (int u = 0; u < 16; ++u) {
                    uint32_t pk; CVT_BF16X2(pk, v[u].x, v[u].y);
                    STS_B32(aWarp + (half * 16 + u) * A_STRIDE + 256 + lane * 4, pk);
                }
            }
        }
        __syncwarp();

        // ---- layer 1: two [16x192]@[192x64] sub-tiles sharing B fragments ----
        float acc[2][8][4];
        #pragma unroll
        for (int s = 0; s < 2; ++s)
            #pragma unroll
            for (int j = 0; j < 8; ++j)
                #pragma unroll
                for (int q = 0; q < 4; ++q) acc[s][j][q] = 0.f;

        #pragma unroll
        for (int kt = 0; kt < 12; ++kt) {
            uint32_t a0[4], a1[4];
            LDSM_X4(a0[0], a0[1], a0[2], a0[3], aBase0 + kt * 32);
            LDSM_X4(a1[0], a1[1], a1[2], a1[3], aBase1 + kt * 32);
            #pragma unroll
            for (int j = 0; j < 8; ++j) {
                uint32_t b0v, b1v;
                LDS_V2(b0v, b1v, w1Base + j * 8 * W1_STRIDE + kt * 32);
                MMA_16816(acc[0][j], a0, b0v, b1v);
                MMA_16816(acc[1][j], a1, b0v, b1v);
            }
        }

        // ---- epilogue 1: bias + relu + repack C -> A fragments ----
        uint32_t a2[2][4][4];
        #pragma unroll
        for (int s = 0; s < 2; ++s)
            #pragma unroll
            for (int j = 0; j < 8; ++j) {
                const float2 bb = *(const float2*)(sB1 + j * 8 + tg * 2);
                const float h0 = fmaxf(acc[s][j][0] + bb.x, 0.f);
                const float h1 = fmaxf(acc[s][j][1] + bb.y, 0.f);
                const float h2 = fmaxf(acc[s][j][2] + bb.x, 0.f);
                const float h3 = fmaxf(acc[s][j][3] + bb.y, 0.f);
                CVT_BF16X2(a2[s][j >> 1][(j & 1) * 2 + 0], h0, h1);
                CVT_BF16X2(a2[s][j >> 1][(j & 1) * 2 + 1], h2, h3);
            }

        // ---- layer 2: two [16x64]@[64x64] sub-tiles sharing B fragments ----
        float acc2[2][8][4];
        #pragma unroll
        for (int s = 0; s < 2; ++s)
            #pragma unroll
            for (int j = 0; j < 8; ++j)
                #pragma unroll
                for (int q = 0; q < 4; ++q) acc2[s][j][q] = 0.f;

        #pragma unroll
        for (int kt = 0; kt < 4; ++kt) {
            #pragma unroll
            for (int j = 0; j < 8; ++j) {
                uint32_t b0v, b1v;
                LDS_V2(b0v, b1v, w2Base + j * 8 * W2_STRIDE + kt * 32);
                MMA_16816(acc2[0][j], a2[0][kt], b0v, b1v);
                MMA_16816(acc2[1][j], a2[1][kt], b0v, b1v);
            }
        }

        // ---- epilogue 2: bias + relu + dot(w3), group-of-4 reduce ----
        #pragma unroll
        for (int s = 0; s < 2; ++s) {
            float plo = 0.f, phi = 0.f;
            #pragma unroll
            for (int j = 0; j < 8; ++j) {
                const int col = j * 8 + tg * 2;
                const float2 bb = *(const float2*)(sB2 + col);
                const float2 ww = *(const float2*)(sW3 + col);
                const float v0 = fmaxf(acc2[s][j][0] + bb.x, 0.f);
                const float v1 = fmaxf(acc2[s][j][1] + bb.y, 0.f);
                const float v2 = fmaxf(acc2[s][j][2] + bb.x, 0.f);
                const float v3 = fmaxf(acc2[s][j][3] + bb.y, 0.f);
                plo = fmaf(v0, ww.x, fmaf(v1, ww.y, plo));
                phi = fmaf(v2, ww.x, fmaf(v3, ww.y, phi));
            }
            #pragma unroll
            for (int o = 1; o <= 2; o <<= 1) {
                plo += __shfl_xor_sync(0xffffffffu, plo, o);
                phi += __shfl_xor_sync(0xffffffffu, phi, o);
            }
            if (tg == 0) {
                const int gr = r0 + s * 16 + g;
                if (gr < nRows)     g_scores[gr]     = plo + b3v;
                if (gr + 8 < nRows) g_scores[gr + 8] = phi + b3v;
            }
        }
        __syncwarp();   // A slab reuse in next iteration
    }
}

// ============================================================================
__global__ void __launch_bounds__(256)
softmax_agg_kernel(const int* __restrict__ hva,
                   const float* __restrict__ a2e,
                   float* __restrict__ out, int nNodes)
{
    __shared__ float sAtt[8][52];
    __shared__ int   sIdx[8][52];
    const int lane = threadIdx.x & 31;
    const int wid  = threadIdx.x >> 5;
    const int n = blockIdx.x * 8 + wid;
    if (n >= nNodes) return;

    const float s1 = g_scores[n * L + lane];
    const bool has2 = lane < (L - 32);
    const float s2 = has2 ? g_scores[n * L + 32 + lane] : -1e30f;
    sIdx[wid][lane] = hva[n * L + lane];
    if (has2) sIdx[wid][32 + lane] = hva[n * L + 32 + lane];

    float m = fmaxf(s1, s2);
    #pragma unroll
    for (int o = 16; o > 0; o >>= 1)
        m = fmaxf(m, __shfl_xor_sync(0xffffffffu, m, o));
    const float e1 = __expf(s1 - m);
    const float e2 = has2 ? __expf(s2 - m) : 0.f;
    float ss = e1 + e2;
    #pragma unroll
    for (int o = 16; o > 0; o >>= 1)
        ss += __shfl_xor_sync(0xffffffffu, ss, o);
    const float inv = 1.f / ss;
    sAtt[wid][lane] = e1 * inv;
    if (has2) sAtt[wid][32 + lane] = e2 * inv;
    __syncwarp();

    float oa = 0.f, ob = 0.f;
    #pragma unroll 10
    for (int l = 0; l < L; ++l) {
        const float2 v =
            reinterpret_cast<const float2*>(a2e + (size_t)sIdx[wid][l] * D)[lane];
        const float att = sAtt[wid][l];
        oa = fmaf(att, v.x, oa);
        ob = fmaf(att, v.y, ob);
    }
    reinterpret_cast<float2*>(out + (size_t)n * D)[lane] = make_float2(oa, ob);
}

// ============================================================================
extern "C" void kernel_launch(void* const* d_in, const int* in_sizes, int n_in,
                              void* d_out, int out_size)
{
    const int*   nodes = (const int*)  d_in[0];
    const int*   hva   = (const int*)  d_in[1];
    const int*   haf   = (const int*)  d_in[2];
    const float* v2e   = (const float*)d_in[3];
    const float* a2e   = (const float*)d_in[4];
    const float* f2e   = (const float*)d_in[5];
    const float* W1    = (const float*)d_in[6];
    const float* b1    = (const float*)d_in[7];
    const float* W2    = (const float*)d_in[8];
    const float* b2    = (const float*)d_in[9];
    const float* w3    = (const float*)d_in[10];
    const float* b3    = (const float*)d_in[11];
    float* out = (float*)d_out;

    const int nNodes = in_sizes[0];
    const int nRows  = nNodes * L;
    const int nT32   = (nRows + ROWS_W - 1) / ROWS_W;
    const int grid2  = (nNodes + 7) / 8;

    cudaFuncSetAttribute(mlp_score_kernel,
                         cudaFuncAttributeMaxDynamicSharedMemorySize, SMEM_BYTES);

    // mlp_score_kernel stays at global launch #4 (= the ncu capture window).
    prep_w1_kernel<<<(K1 * D + 255) / 256, 256>>>(W1);
    prep_w2_kernel<<<(D * D + 255) / 256, 256>>>(W2);
    prep_bias_kernel<<<1, 256>>>(b1, b2, w3, b3);
    mlp_score_kernel<<<GRID1, THREADS1, SMEM_BYTES>>>(
        nodes, hva, haf, v2e, a2e, f2e, nT32, nNodes, nRows);
    softmax_agg_kernel<<<grid2, 256>>>(hva, a2e, out, nNodes);
}

// round 11
// speedup vs baseline: 1.1945x; 1.0043x over previous
#include <cuda_runtime.h>
#include <cuda_bf16.h>
#include <cstdint>

// ============================================================================
// VA_Aggregator via mma.sync bf16 HMMA (sm_103 baseline PTX; no tcgen05).
// K0a: W1 (va+af halves only) -> bf16 interleaved image
// K0b: W2 -> bf16 interleaved image
// K0c: per-node c[node] = b1 + rep(node) @ W1[64:128]  (fp32, exact) + bias pack
// K1 (persistent, warp-autonomous): 16-row warp tiles; layer1 K=128 via
//     c-node trick (-25% tensor ops, -33% layer1 LDS/STS/ldsm vs R7).
// K2: per-node softmax over L=50 + fp32 weighted gather of e_va (unroll 25).
// ============================================================================

constexpr int L      = 50;
constexpr int D      = 64;
constexpr int NMAX_ROWS  = 8192 * 50;
constexpr int NMAX_NODES = 8192;
constexpr int GRID1  = 296;
constexpr int WARPS1 = 8;

__device__ float g_scores[NMAX_ROWS];
__device__ float g_cnode[NMAX_NODES * D];      // b1 + rep @ W1[64:128], fp32
__device__ float g_bias[192];                  // [0:64)=b2 [64:128)=w3 [128]=b3

// ---- SMEM layout (bytes from dynamic smem base) ----
constexpr int A_STRIDE  = 272;                 // 128*2 + 16 pad (ldsm conflict-free)
constexpr int W1_STRIDE = 288;                 // 72 words ≡ 8 mod 32 (conflict-free)
constexpr int W2_STRIDE = 160;                 // 40 words  ≡ 8 mod 32
constexpr int W1_BYTES  = 64 * W1_STRIDE;      // 18432 (k = 0..127: va|af)
constexpr int W2_BYTES  = 64 * W2_STRIDE;      // 10240
constexpr int A_BYTES   = WARPS1 * 16 * A_STRIDE;        // 34816
constexpr int OFF_A    = 0;
constexpr int OFF_W1   = A_BYTES;                        // 34816
constexpr int OFF_W2   = OFF_W1 + W1_BYTES;              // 53248
constexpr int OFF_BIAS = OFF_W2 + W2_BYTES;              // 63488 (192 f, pad 1024)
constexpr int OFF_CN   = OFF_BIAS + 1024;                // 64512: 8 warps x 2 x 64 f
constexpr int SMEM_BYTES = OFF_CN + 4096 + 32;           // ~68640

__device__ __align__(16) uint8_t g_w1img[W1_BYTES];
__device__ __align__(16) uint8_t g_w2img[W2_BYTES];

__device__ __forceinline__ uint32_t smem_u32(const void* p) {
    uint32_t a;
    asm("{ .reg .u64 t; cvta.to.shared.u64 t, %1; cvt.u32.u64 %0, t; }"
        : "=r"(a) : "l"(p));
    return a;
}

#define CVT_BF16X2(res, lo, hi) \
    asm("cvt.rn.satfinite.bf16x2.f32 %0, %1, %2;" : "=r"(res) : "f"(hi), "f"(lo))

#define LDSM_X4(r0, r1, r2, r3, addr) \
    asm volatile("ldmatrix.sync.aligned.m8n8.x4.shared.b16 {%0,%1,%2,%3}, [%4];" \
                 : "=r"(r0), "=r"(r1), "=r"(r2), "=r"(r3) : "r"(addr))

#define LDS_V2(r0, r1, addr) \
    asm volatile("ld.shared.v2.u32 {%0,%1}, [%2];" \
                 : "=r"(r0), "=r"(r1) : "r"(addr))

#define STS_B32(addr, val) \
    asm volatile("st.shared.b32 [%0], %1;" :: "r"(addr), "r"(val) : "memory")

#define MMA_16816(c, a, b0, b1) \
    asm volatile("mma.sync.aligned.m16n8k16.row.col.f32.bf16.bf16.f32 " \
                 "{%0,%1,%2,%3}, {%4,%5,%6,%7}, {%8,%9}, {%0,%1,%2,%3};" \
                 : "+f"((c)[0]), "+f"((c)[1]), "+f"((c)[2]), "+f"((c)[3]) \
                 : "r"((a)[0]), "r"((a)[1]), "r"((a)[2]), "r"((a)[3]), \
                   "r"(b0), "r"(b1))

// Wt interleaved byte offset: B-fragment {k, k+1, k+8, k+9} contiguous as 8B.
__device__ __forceinline__ int wt_off(int n, int k, int stride) {
    const int kt = k >> 4, kk = k & 15;
    return n * stride + kt * 32 + ((kk & 7) >> 1) * 8 + ((kk >= 8) ? 4 : 0) + (kk & 1) * 2;
}

// ============================================================================
// K0a: W1 va/af halves (k 0..63 -> W1 rows 0..63, k 64..127 -> rows 128..191)
__global__ void __launch_bounds__(256)
prep_w1_kernel(const float* __restrict__ W1)
{
    const int i = blockIdx.x * 256 + threadIdx.x;
    if (i < 128 * D) {
        const int k2 = i >> 6, n = i & 63;
        const int k  = (k2 < 64) ? k2 : (k2 + 64);
        *(__nv_bfloat16*)(g_w1img + wt_off(n, k2, W1_STRIDE)) =
            __float2bfloat16(W1[k * 64 + n]);
    }
}

__global__ void __launch_bounds__(256)
prep_w2_kernel(const float* __restrict__ W2)
{
    const int i = blockIdx.x * 256 + threadIdx.x;
    if (i < D * D) {
        const int k = i >> 6, n = i & 63;
        *(__nv_bfloat16*)(g_w2img + wt_off(n, k, W2_STRIDE)) = __float2bfloat16(W2[i]);
    }
}

// K0c: c[node] = b1 + v2e[nodes[node]] @ W1[64:128]  (fp32) + bias pack
__global__ void __launch_bounds__(256)
prep_cnode_kernel(const int* __restrict__ nodes,
                  const float* __restrict__ v2e,
                  const float* __restrict__ W1,
                  const float* __restrict__ b1,
                  const float* __restrict__ b2,
                  const float* __restrict__ w3,
                  const float* __restrict__ b3,
                  int nNodes)
{
    __shared__ float sW[64 * 64];
    const int tid  = threadIdx.x;
    const int lane = tid & 31;
    const int wid  = tid >> 5;

    for (int i = tid; i < 64 * 64; i += 256)
        sW[i] = W1[(64 + (i >> 6)) * 64 + (i & 63)];
    if (blockIdx.x == 0) {
        if (tid < 64)                      g_bias[tid] = b2[tid];
        else if (tid < 128)                g_bias[tid] = w3[tid - 64];
        else if (tid == 128)               g_bias[128] = b3[0];
    }
    __syncthreads();

    const int node = blockIdx.x * 8 + wid;
    if (node >= nNodes) return;
    const int item = nodes[node];
    const float2 myrep = ((const float2*)(v2e + (size_t)item * D))[lane];

    float c0 = b1[lane], c1 = b1[lane + 32];
    #pragma unroll
    for (int k = 0; k < 64; ++k) {
        const float rk = __shfl_sync(0xffffffffu, (k & 1) ? myrep.y : myrep.x, k >> 1);
        c0 = fmaf(rk, sW[k * 64 + lane],      c0);
        c1 = fmaf(rk, sW[k * 64 + lane + 32], c1);
    }
    g_cnode[node * D + lane]      = c0;
    g_cnode[node * D + lane + 32] = c1;
}

// ============================================================================
__global__ void __launch_bounds__(32 * WARPS1, 2)
mlp_score_kernel(const int* __restrict__ hva,
                 const int* __restrict__ haf,
                 const float* __restrict__ a2e,
                 const float* __restrict__ f2e,
                 int nT16, int nNodes, int nRows)
{
    extern __shared__ char sm[];
    const uint32_t sbase = smem_u32(sm);

    const int tid  = threadIdx.x;
    const int lane = tid & 31;
    const int wid  = tid >> 5;

    float* sBias = (float*)(sm + OFF_BIAS);
    float* sB2 = sBias;
    float* sW3 = sBias + 64;

    // ---- stage weights once per CTA ----
    {
        const uint4* s1 = (const uint4*)g_w1img;
        const uint4* s2 = (const uint4*)g_w2img;
        uint4* d1 = (uint4*)(sm + OFF_W1);
        uint4* d2 = (uint4*)(sm + OFF_W2);
        #pragma unroll 2
        for (int i = tid; i < W1_BYTES / 16; i += 32 * WARPS1) d1[i] = s1[i];
        for (int i = tid; i < W2_BYTES / 16; i += 32 * WARPS1) d2[i] = s2[i];
        if (tid < 192) sBias[tid] = g_bias[tid];
    }
    __syncthreads();

    const int g  = lane >> 2;
    const int tg = lane & 3;
    const uint32_t aWarp  = sbase + OFF_A + wid * 16 * A_STRIDE;
    const uint32_t aBase  = aWarp + (lane & 15) * A_STRIDE + (lane >> 4) * 16;
    const uint32_t w1Base = sbase + OFF_W1 + g * W1_STRIDE + tg * 8;
    const uint32_t w2Base = sbase + OFF_W2 + g * W2_STRIDE + tg * 8;
    float* sCn = (float*)(sm + OFF_CN) + wid * 128;   // [2][64]

    const int gwarp = blockIdx.x * WARPS1 + wid;
    const int totalWarps = GRID1 * WARPS1;
    const float b3v = sBias[128];

    for (int t = gwarp; t < nT16; t += totalWarps) {
        const int r0 = t * 16;

        // ---- own history indices: lanes 0-15 -> va, lanes 16-31 -> af ----
        int rr = r0 + (lane & 15);
        if (rr > nRows - 1) rr = nRows - 1;
        const int myIdx = (lane < 16) ? hva[rr] : haf[rr];

        // ---- c-node vectors: 16 rows span at most 2 nodes ----
        const int node0  = r0 / L;
        const int nbound = (node0 + 1) * L - r0;     // rows [0, nbound) -> node0
        int n1 = node0 + 1; if (n1 > nNodes - 1) n1 = nNodes - 1;
        {
            const float2 c0 = ((const float2*)(g_cnode + node0 * D))[lane];
            const float2 c1 = ((const float2*)(g_cnode + n1    * D))[lane];
            ((float2*)sCn)[lane]      = c0;
            ((float2*)sCn)[32 + lane] = c1;
        }

        // ---- gather e_va rows (16 LDG.64 in flight) ----
        {
            float2 v[16];
            #pragma unroll
            for (int u = 0; u < 16; ++u) {
                const int idx = __shfl_sync(0xffffffffu, myIdx, u);
                v[u] = ((const float2*)(a2e + (size_t)idx * D))[lane];
            }
            #pragma unroll
            for (int u = 0; u < 16; ++u) {
                uint32_t pk; CVT_BF16X2(pk, v[u].x, v[u].y);
                STS_B32(aWarp + u * A_STRIDE + lane * 4, pk);
            }
        }
        // ---- gather e_af rows ----
        {
            float2 v[16];
            #pragma unroll
            for (int u = 0; u < 16; ++u) {
                const int idx = __shfl_sync(0xffffffffu, myIdx, u + 16);
                v[u] = ((const float2*)(f2e + (size_t)idx * D))[lane];
            }
            #pragma unroll
            for (int u = 0; u < 16; ++u) {
                uint32_t pk; CVT_BF16X2(pk, v[u].x, v[u].y);
                STS_B32(aWarp + u * A_STRIDE + 128 + lane * 4, pk);
            }
        }
        __syncwarp();

        // ---- layer 1: [16x128] @ [128x64] (rep folded into c-node) ----
        float acc[8][4];
        #pragma unroll
        for (int j = 0; j < 8; ++j)
            #pragma unroll
            for (int q = 0; q < 4; ++q) acc[j][q] = 0.f;

        #pragma unroll
        for (int kt = 0; kt < 8; ++kt) {
            uint32_t a[4];
            LDSM_X4(a[0], a[1], a[2], a[3], aBase + kt * 32);
            #pragma unroll
            for (int j = 0; j < 8; ++j) {
                uint32_t b0v, b1v;
                LDS_V2(b0v, b1v, w1Base + j * 8 * W1_STRIDE + kt * 32);
                MMA_16816(acc[j], a, b0v, b1v);
            }
        }

        // ---- epilogue 1: +c-node(row) + relu + repack C -> A fragments ----
        const int sel0 = (g     < nbound) ? 0 : 64;
        const int sel1 = (g + 8 < nbound) ? 0 : 64;
        uint32_t a2[4][4];
        #pragma unroll
        for (int j = 0; j < 8; ++j) {
            const int col = j * 8 + tg * 2;
            const float2 cA = *(const float2*)(sCn + sel0 + col);
            const float2 cB = *(const float2*)(sCn + sel1 + col);
            const float h0 = fmaxf(acc[j][0] + cA.x, 0.f);
            const float h1 = fmaxf(acc[j][1] + cA.y, 0.f);
            const float h2 = fmaxf(acc[j][2] + cB.x, 0.f);
            const float h3 = fmaxf(acc[j][3] + cB.y, 0.f);
            CVT_BF16X2(a2[j >> 1][(j & 1) * 2 + 0], h0, h1);
            CVT_BF16X2(a2[j >> 1][(j & 1) * 2 + 1], h2, h3);
        }

        // ---- layer 2: [16x64] @ [64x64] (A from registers) ----
        float acc2[8][4];
        #pragma unroll
        for (int j = 0; j < 8; ++j)
            #pragma unroll
            for (int q = 0; q < 4; ++q) acc2[j][q] = 0.f;

        #pragma unroll
        for (int kt = 0; kt < 4; ++kt) {
            #pragma unroll
            for (int j = 0; j < 8; ++j) {
                uint32_t b0v, b1v;
                LDS_V2(b0v, b1v, w2Base + j * 8 * W2_STRIDE + kt * 32);
                MMA_16816(acc2[j], a2[kt], b0v, b1v);
            }
        }

        // ---- epilogue 2: bias + relu + dot(w3), group-of-4 reduce ----
        float plo = 0.f, phi = 0.f;
        #pragma unroll
        for (int j = 0; j < 8; ++j) {
            const int col = j * 8 + tg * 2;
            const float2 bb = *(const float2*)(sB2 + col);
            const float2 ww = *(const float2*)(sW3 + col);
            const float v0 = fmaxf(acc2[j][0] + bb.x, 0.f);
            const float v1 = fmaxf(acc2[j][1] + bb.y, 0.f);
            const float v2 = fmaxf(acc2[j][2] + bb.x, 0.f);
            const float v3 = fmaxf(acc2[j][3] + bb.y, 0.f);
            plo = fmaf(v0, ww.x, fmaf(v1, ww.y, plo));
            phi = fmaf(v2, ww.x, fmaf(v3, ww.y, phi));
        }
        #pragma unroll
        for (int o = 1; o <= 2; o <<= 1) {
            plo += __shfl_xor_sync(0xffffffffu, plo, o);
            phi += __shfl_xor_sync(0xffffffffu, phi, o);
        }
        if (tg == 0) {
            const int gr = r0 + g;
            if (gr < nRows)     g_scores[gr]     = plo + b3v;
            if (gr + 8 < nRows) g_scores[gr + 8] = phi + b3v;
        }
        __syncwarp();   // A slab + sCn reuse in next iteration
    }
}

// ============================================================================
__global__ void __launch_bounds__(256)
softmax_agg_kernel(const int* __restrict__ hva,
                   const float* __restrict__ a2e,
                   float* __restrict__ out, int nNodes)
{
    __shared__ float sAtt[8][52];
    __shared__ int   sIdx[8][52];
    const int lane = threadIdx.x & 31;
    const int wid  = threadIdx.x >> 5;
    const int n = blockIdx.x * 8 + wid;
    if (n >= nNodes) return;

    const float s1 = g_scores[n * L + lane];
    const bool has2 = lane < (L - 32);
    const float s2 = has2 ? g_scores[n * L + 32 + lane] : -1e30f;
    sIdx[wid][lane] = hva[n * L + lane];
    if (has2) sIdx[wid][32 + lane] = hva[n * L + 32 + lane];

    float m = fmaxf(s1, s2);
    #pragma unroll
    for (int o = 16; o > 0; o >>= 1)
        m = fmaxf(m, __shfl_xor_sync(0xffffffffu, m, o));
    const float e1 = __expf(s1 - m);
    const float e2 = has2 ? __expf(s2 - m) : 0.f;
    float ss = e1 + e2;
    #pragma unroll
    for (int o = 16; o > 0; o >>= 1)
        ss += __shfl_xor_sync(0xffffffffu, ss, o);
    const float inv = 1.f / ss;
    sAtt[wid][lane] = e1 * inv;
    if (has2) sAtt[wid][32 + lane] = e2 * inv;
    __syncwarp();

    float oa = 0.f, ob = 0.f;
    #pragma unroll 25
    for (int l = 0; l < L; ++l) {
        const float2 v =
            reinterpret_cast<const float2*>(a2e + (size_t)sIdx[wid][l] * D)[lane];
        const float att = sAtt[wid][l];
        oa = fmaf(att, v.x, oa);
        ob = fmaf(att, v.y, ob);
    }
    reinterpret_cast<float2*>(out + (size_t)n * D)[lane] = make_float2(oa, ob);
}

// ============================================================================
extern "C" void kernel_launch(void* const* d_in, const int* in_sizes, int n_in,
                              void* d_out, int out_size)
{
    const int*   nodes = (const int*)  d_in[0];
    const int*   hva   = (const int*)  d_in[1];
    const int*   haf   = (const int*)  d_in[2];
    const float* v2e   = (const float*)d_in[3];
    const float* a2e   = (const float*)d_in[4];
    const float* f2e   = (const float*)d_in[5];
    const float* W1    = (const float*)d_in[6];
    const float* b1    = (const float*)d_in[7];
    const float* W2    = (const float*)d_in[8];
    const float* b2    = (const float*)d_in[9];
    const float* w3    = (const float*)d_in[10];
    const float* b3    = (const float*)d_in[11];
    float* out = (float*)d_out;

    const int nNodes = in_sizes[0];
    const int nRows  = nNodes * L;
    const int nT16   = (nRows + 15) / 16;
    const int grid2  = (nNodes + 7) / 8;
    const int gridCn = (nNodes + 7) / 8;

    cudaFuncSetAttribute(mlp_score_kernel,
                         cudaFuncAttributeMaxDynamicSharedMemorySize, SMEM_BYTES);

    // mlp_score_kernel stays at global launch #4 (= the ncu capture window).
    prep_w1_kernel<<<(128 * D + 255) / 256, 256>>>(W1);
    prep_w2_kernel<<<(D * D + 255) / 256, 256>>>(W2);
    prep_cnode_kernel<<<gridCn, 256>>>(nodes, v2e, W1, b1, b2, w3, b3, nNodes);
    mlp_score_kernel<<<GRID1, 32 * WARPS1, SMEM_BYTES>>>(
        hva, haf, a2e, f2e, nT16, nNodes, nRows);
    softmax_agg_kernel<<<grid2, 256>>>(hva, a2e, out, nNodes);
}

// round 12
// speedup vs baseline: 1.3421x; 1.1235x over previous
#include <cuda_runtime.h>
#include <cuda_bf16.h>
#include <cstdint>

// ============================================================================
// VA_Aggregator via mma.sync bf16 HMMA (sm_103 baseline PTX; no tcgen05).
// K0 (fused prep): W1 va/af halves + W2 -> bf16 interleaved images;
//     c[node] = b1 + rep(node) @ W1[64:128] (fp32); bias pack.
// K1 (persistent, warp-autonomous): 32-row warp tiles (two 16-row MMA
//     sub-tiles sharing each weight-fragment LDS), K=128 layer1 via c-node.
//     8 warps/CTA, 2 CTA/SM (128-reg cap) = 16 warps/SM + halved weight LDS.
// K2: per-node softmax over L=50 + fp32 weighted gather of e_va.
// ============================================================================

constexpr int L      = 50;
constexpr int D      = 64;
constexpr int NMAX_ROWS  = 8192 * 50;
constexpr int NMAX_NODES = 8192;
constexpr int GRID1  = 296;
constexpr int WARPS1 = 8;
constexpr int ROWS_W = 32;

__device__ float g_scores[NMAX_ROWS];
__device__ float g_cnode[NMAX_NODES * D];      // b1 + rep @ W1[64:128], fp32
__device__ float g_bias[192];                  // [0:64)=b2 [64:128)=w3 [128]=b3

// ---- SMEM layout (bytes from dynamic smem base) ----
constexpr int A_STRIDE  = 272;                 // 128*2 + 16 pad (ldsm conflict-free)
constexpr int W1_STRIDE = 288;                 // 72 words ≡ 8 mod 32 (conflict-free)
constexpr int W2_STRIDE = 160;                 // 40 words ≡ 8 mod 32
constexpr int W1_BYTES  = 64 * W1_STRIDE;      // 18432 (k = 0..127: va|af)
constexpr int W2_BYTES  = 64 * W2_STRIDE;      // 10240
constexpr int A_BYTES   = WARPS1 * ROWS_W * A_STRIDE;    // 69632
constexpr int OFF_A    = 0;
constexpr int OFF_W1   = A_BYTES;                        // 69632
constexpr int OFF_W2   = OFF_W1 + W1_BYTES;              // 88064
constexpr int OFF_BIAS = OFF_W2 + W2_BYTES;              // 98304
constexpr int OFF_CN   = OFF_BIAS + 1024;                // 99328: 8 w x 128 f
constexpr int SMEM_BYTES = OFF_CN + 4096 + 32;           // ~103456

__device__ __align__(16) uint8_t g_w1img[W1_BYTES];
__device__ __align__(16) uint8_t g_w2img[W2_BYTES];

__device__ __forceinline__ uint32_t smem_u32(const void* p) {
    uint32_t a;
    asm("{ .reg .u64 t; cvta.to.shared.u64 t, %1; cvt.u32.u64 %0, t; }"
        : "=r"(a) : "l"(p));
    return a;
}

#define CVT_BF16X2(res, lo, hi) \
    asm("cvt.rn.satfinite.bf16x2.f32 %0, %1, %2;" : "=r"(res) : "f"(hi), "f"(lo))

#define LDSM_X4(r0, r1, r2, r3, addr) \
    asm volatile("ldmatrix.sync.aligned.m8n8.x4.shared.b16 {%0,%1,%2,%3}, [%4];" \
                 : "=r"(r0), "=r"(r1), "=r"(r2), "=r"(r3) : "r"(addr))

#define LDS_V2(r0, r1, addr) \
    asm volatile("ld.shared.v2.u32 {%0,%1}, [%2];" \
                 : "=r"(r0), "=r"(r1) : "r"(addr))

#define STS_B32(addr, val) \
    asm volatile("st.shared.b32 [%0], %1;" :: "r"(addr), "r"(val) : "memory")

#define MMA_16816(c, a, b0, b1) \
    asm volatile("mma.sync.aligned.m16n8k16.row.col.f32.bf16.bf16.f32 " \
                 "{%0,%1,%2,%3}, {%4,%5,%6,%7}, {%8,%9}, {%0,%1,%2,%3};" \
                 : "+f"((c)[0]), "+f"((c)[1]), "+f"((c)[2]), "+f"((c)[3]) \
                 : "r"((a)[0]), "r"((a)[1]), "r"((a)[2]), "r"((a)[3]), \
                   "r"(b0), "r"(b1))

// Wt interleaved byte offset: B-fragment {k, k+1, k+8, k+9} contiguous as 8B.
__device__ __forceinline__ int wt_off(int n, int k, int stride) {
    const int kt = k >> 4, kk = k & 15;
    return n * stride + kt * 32 + ((kk & 7) >> 1) * 8 + ((kk >= 8) ? 4 : 0) + (kk & 1) * 2;
}

// ============================================================================
// K0: fused prep. blocks [0, nCn) = cnode (+bias on block 0),
//     [nCn, nCn+32) = W1 image, [nCn+32, nCn+48) = W2 image.
__global__ void __launch_bounds__(256)
prep_all_kernel(const int* __restrict__ nodes,
                const float* __restrict__ v2e,
                const float* __restrict__ W1,
                const float* __restrict__ W2,
                const float* __restrict__ b1,
                const float* __restrict__ b2,
                const float* __restrict__ w3,
                const float* __restrict__ b3,
                int nNodes, int nCn)
{
    const int b   = blockIdx.x;
    const int tid = threadIdx.x;

    if (b >= nCn + 32) {                 // ---- W2 image ----
        const int i = (b - nCn - 32) * 256 + tid;
        if (i < D * D) {
            const int k = i >> 6, n = i & 63;
            *(__nv_bfloat16*)(g_w2img + wt_off(n, k, W2_STRIDE)) =
                __float2bfloat16(W2[i]);
        }
        return;
    }
    if (b >= nCn) {                      // ---- W1 image (va|af halves) ----
        const int i = (b - nCn) * 256 + tid;
        if (i < 128 * D) {
            const int k2 = i >> 6, n = i & 63;
            const int k  = (k2 < 64) ? k2 : (k2 + 64);
            *(__nv_bfloat16*)(g_w1img + wt_off(n, k2, W1_STRIDE)) =
                __float2bfloat16(W1[k * 64 + n]);
        }
        return;
    }

    // ---- cnode: c[node] = b1 + rep @ W1[64:128] ----
    __shared__ float sW[64 * 64];
    const int lane = tid & 31;
    const int wid  = tid >> 5;

    for (int i = tid; i < 64 * 64; i += 256)
        sW[i] = W1[(64 + (i >> 6)) * 64 + (i & 63)];
    if (b == 0) {
        if (tid < 64)        g_bias[tid] = b2[tid];
        else if (tid < 128)  g_bias[tid] = w3[tid - 64];
        else if (tid == 128) g_bias[128] = b3[0];
    }
    __syncthreads();

    const int node = b * 8 + wid;
    if (node >= nNodes) return;
    const int item = nodes[node];
    const float2 myrep = ((const float2*)(v2e + (size_t)item * D))[lane];

    float c0 = b1[lane], c1 = b1[lane + 32];
    #pragma unroll
    for (int k = 0; k < 64; ++k) {
        const float rk = __shfl_sync(0xffffffffu, (k & 1) ? myrep.y : myrep.x, k >> 1);
        c0 = fmaf(rk, sW[k * 64 + lane],      c0);
        c1 = fmaf(rk, sW[k * 64 + lane + 32], c1);
    }
    g_cnode[node * D + lane]      = c0;
    g_cnode[node * D + lane + 32] = c1;
}

// ============================================================================
__global__ void __launch_bounds__(32 * WARPS1, 2)
mlp_score_kernel(const int* __restrict__ hva,
                 const int* __restrict__ haf,
                 const float* __restrict__ a2e,
                 const float* __restrict__ f2e,
                 int nT32, int nNodes, int nRows)
{
    extern __shared__ char sm[];
    const uint32_t sbase = smem_u32(sm);

    const int tid  = threadIdx.x;
    const int lane = tid & 31;
    const int wid  = tid >> 5;

    float* sBias = (float*)(sm + OFF_BIAS);
    float* sB2 = sBias;
    float* sW3 = sBias + 64;

    // ---- stage weights once per CTA ----
    {
        const uint4* s1 = (const uint4*)g_w1img;
        const uint4* s2 = (const uint4*)g_w2img;
        uint4* d1 = (uint4*)(sm + OFF_W1);
        uint4* d2 = (uint4*)(sm + OFF_W2);
        #pragma unroll 2
        for (int i = tid; i < W1_BYTES / 16; i += 32 * WARPS1) d1[i] = s1[i];
        for (int i = tid; i < W2_BYTES / 16; i += 32 * WARPS1) d2[i] = s2[i];
        if (tid < 192) sBias[tid] = g_bias[tid];
    }
    __syncthreads();

    const int g  = lane >> 2;
    const int tg = lane & 3;
    const uint32_t aWarp  = sbase + OFF_A + wid * ROWS_W * A_STRIDE;
    const uint32_t aBase0 = aWarp + (lane & 15) * A_STRIDE + (lane >> 4) * 16;
    const uint32_t aBase1 = aBase0 + 16 * A_STRIDE;
    const uint32_t w1Base = sbase + OFF_W1 + g * W1_STRIDE + tg * 8;
    const uint32_t w2Base = sbase + OFF_W2 + g * W2_STRIDE + tg * 8;
    float* sCn = (float*)(sm + OFF_CN) + wid * 128;   // [2][64]

    const int gwarp = blockIdx.x * WARPS1 + wid;
    const int totalWarps = GRID1 * WARPS1;
    const float b3v = sBias[128];

    for (int t = gwarp; t < nT32; t += totalWarps) {
        const int r0 = t * ROWS_W;

        // ---- own history indices for all 32 rows ----
        int rr = r0 + lane;
        if (rr > nRows - 1) rr = nRows - 1;
        const int myVa = hva[rr];
        const int myAf = haf[rr];

        // ---- c-node vectors: 32 rows span at most 2 nodes ----
        const int node0  = r0 / L;
        const int nbound = (node0 + 1) * L - r0;     // rows [0, nbound) -> node0
        int n1 = node0 + 1; if (n1 > nNodes - 1) n1 = nNodes - 1;
        {
            const float2 c0 = ((const float2*)(g_cnode + node0 * D))[lane];
            const float2 c1 = ((const float2*)(g_cnode + n1    * D))[lane];
            ((float2*)sCn)[lane]      = c0;
            ((float2*)sCn)[32 + lane] = c1;
        }

        // ---- gather e_va / e_af rows: 4 batches of 16 LDG.64 in flight ----
        #pragma unroll
        for (int half = 0; half < 2; ++half) {
            {
                float2 v[16];
                #pragma unroll
                for (int u = 0; u < 16; ++u) {
                    const int idx = __shfl_sync(0xffffffffu, myVa, half * 16 + u);
                    v[u] = ((const float2*)(a2e + (size_t)idx * D))[lane];
                }
                #pragma unroll
                for (int u = 0; u < 16; ++u) {
                    uint32_t pk; CVT_BF16X2(pk, v[u].x, v[u].y);
                    STS_B32(aWarp + (half * 16 + u) * A_STRIDE + lane * 4, pk);
                }
            }
            {
                float2 v[16];
                #pragma unroll
                for (int u = 0; u < 16; ++u) {
                    const int idx = __shfl_sync(0xffffffffu, myAf, half * 16 + u);
                    v[u] = ((const float2*)(f2e + (size_t)idx * D))[lane];
                }
                #pragma unroll
                for (int u = 0; u < 16; ++u) {
                    uint32_t pk; CVT_BF16X2(pk, v[u].x, v[u].y);
                    STS_B32(aWarp + (half * 16 + u) * A_STRIDE + 128 + lane * 4, pk);
                }
            }
        }
        __syncwarp();

        // ---- layer 1: two [16x128]@[128x64] sub-tiles sharing B fragments ----
        float acc[2][8][4];
        #pragma unroll
        for (int s = 0; s < 2; ++s)
            #pragma unroll
            for (int j = 0; j < 8; ++j)
                #pragma unroll
                for (int q = 0; q < 4; ++q) acc[s][j][q] = 0.f;

        #pragma unroll
        for (int kt = 0; kt < 8; ++kt) {
            uint32_t a0[4], a1[4];
            LDSM_X4(a0[0], a0[1], a0[2], a0[3], aBase0 + kt * 32);
            LDSM_X4(a1[0], a1[1], a1[2], a1[3], aBase1 + kt * 32);
            #pragma unroll
            for (int j = 0; j < 8; ++j) {
                uint32_t b0v, b1v;
                LDS_V2(b0v, b1v, w1Base + j * 8 * W1_STRIDE + kt * 32);
                MMA_16816(acc[0][j], a0, b0v, b1v);
                MMA_16816(acc[1][j], a1, b0v, b1v);
            }
        }

        // ---- epilogue 1: +c-node(row) + relu + repack C -> A fragments ----
        uint32_t a2[2][4][4];
        #pragma unroll
        for (int s = 0; s < 2; ++s) {
            const int i0 = s * 16 + g;
            const int sel0 = (i0     < nbound) ? 0 : 64;
            const int sel1 = (i0 + 8 < nbound) ? 0 : 64;
            #pragma unroll
            for (int j = 0; j < 8; ++j) {
                const int col = j * 8 + tg * 2;
                const float2 cA = *(const float2*)(sCn + sel0 + col);
                const float2 cB = *(const float2*)(sCn + sel1 + col);
                const float h0 = fmaxf(acc[s][j][0] + cA.x, 0.f);
                const float h1 = fmaxf(acc[s][j][1] + cA.y, 0.f);
                const float h2 = fmaxf(acc[s][j][2] + cB.x, 0.f);
                const float h3 = fmaxf(acc[s][j][3] + cB.y, 0.f);
                CVT_BF16X2(a2[s][j >> 1][(j & 1) * 2 + 0], h0, h1);
                CVT_BF16X2(a2[s][j >> 1][(j & 1) * 2 + 1], h2, h3);
            }
        }

        // ---- layer 2: two [16x64]@[64x64] sub-tiles sharing B fragments ----
        float acc2[2][8][4];
        #pragma unroll
        for (int s = 0; s < 2; ++s)
            #pragma unroll
            for (int j = 0; j < 8; ++j)
                #pragma unroll
                for (int q = 0; q < 4; ++q) acc2[s][j][q] = 0.f;

        #pragma unroll
        for (int kt = 0; kt < 4; ++kt) {
            #pragma unroll
            for (int j = 0; j < 8; ++j) {
                uint32_t b0v, b1v;
                LDS_V2(b0v, b1v, w2Base + j * 8 * W2_STRIDE + kt * 32);
                MMA_16816(acc2[0][j], a2[0][kt], b0v, b1v);
                MMA_16816(acc2[1][j], a2[1][kt], b0v, b1v);
            }
        }

        // ---- epilogue 2: bias + relu + dot(w3), group-of-4 reduce ----
        #pragma unroll
        for (int s = 0; s < 2; ++s) {
            float plo = 0.f, phi = 0.f;
            #pragma unroll
            for (int j = 0; j < 8; ++j) {
                const int col = j * 8 + tg * 2;
                const float2 bb = *(const float2*)(sB2 + col);
                const float2 ww = *(const float2*)(sW3 + col);
                const float v0 = fmaxf(acc2[s][j][0] + bb.x, 0.f);
                const float v1 = fmaxf(acc2[s][j][1] + bb.y, 0.f);
                const float v2 = fmaxf(acc2[s][j][2] + bb.x, 0.f);
                const float v3 = fmaxf(acc2[s][j][3] + bb.y, 0.f);
                plo = fmaf(v0, ww.x, fmaf(v1, ww.y, plo));
                phi = fmaf(v2, ww.x, fmaf(v3, ww.y, phi));
            }
            #pragma unroll
            for (int o = 1; o <= 2; o <<= 1) {
                plo += __shfl_xor_sync(0xffffffffu, plo, o);
                phi += __shfl_xor_sync(0xffffffffu, phi, o);
            }
            if (tg == 0) {
                const int gr = r0 + s * 16 + g;
                if (gr < nRows)     g_scores[gr]     = plo + b3v;
                if (gr + 8 < nRows) g_scores[gr + 8] = phi + b3v;
            }
        }
        __syncwarp();   // A slab + sCn reuse in next iteration
    }
}

// ============================================================================
__global__ void __launch_bounds__(256)
softmax_agg_kernel(const int* __restrict__ hva,
                   const float* __restrict__ a2e,
                   float* __restrict__ out, int nNodes)
{
    __shared__ float sAtt[8][52];
    __shared__ int   sIdx[8][52];
    const int lane = threadIdx.x & 31;
    const int wid  = threadIdx.x >> 5;
    const int n = blockIdx.x * 8 + wid;
    if (n >= nNodes) return;

    const float s1 = g_scores[n * L + lane];
    const bool has2 = lane < (L - 32);
    const float s2 = has2 ? g_scores[n * L + 32 + lane] : -1e30f;
    sIdx[wid][lane] = hva[n * L + lane];
    if (has2) sIdx[wid][32 + lane] = hva[n * L + 32 + lane];

    float m = fmaxf(s1, s2);
    #pragma unroll
    for (int o = 16; o > 0; o >>= 1)
        m = fmaxf(m, __shfl_xor_sync(0xffffffffu, m, o));
    const float e1 = __expf(s1 - m);
    const float e2 = has2 ? __expf(s2 - m) : 0.f;
    float ss = e1 + e2;
    #pragma unroll
    for (int o = 16; o > 0; o >>= 1)
        ss += __shfl_xor_sync(0xffffffffu, ss, o);
    const float inv = 1.f / ss;
    sAtt[wid][lane] = e1 * inv;
    if (has2) sAtt[wid][32 + lane] = e2 * inv;
    __syncwarp();

    float oa = 0.f, ob = 0.f;
    #pragma unroll 25
    for (int l = 0; l < L; ++l) {
        const float2 v =
            reinterpret_cast<const float2*>(a2e + (size_t)sIdx[wid][l] * D)[lane];
        const float att = sAtt[wid][l];
        oa = fmaf(att, v.x, oa);
        ob = fmaf(att, v.y, ob);
    }
    reinterpret_cast<float2*>(out + (size_t)n * D)[lane] = make_float2(oa, ob);
}

// ============================================================================
extern "C" void kernel_launch(void* const* d_in, const int* in_sizes, int n_in,
                              void* d_out, int out_size)
{
    const int*   nodes = (const int*)  d_in[0];
    const int*   hva   = (const int*)  d_in[1];
    const int*   haf   = (const int*)  d_in[2];
    const float* v2e   = (const float*)d_in[3];
    const float* a2e   = (const float*)d_in[4];
    const float* f2e   = (const float*)d_in[5];
    const float* W1    = (const float*)d_in[6];
    const float* b1    = (const float*)d_in[7];
    const float* W2    = (const float*)d_in[8];
    const float* b2    = (const float*)d_in[9];
    const float* w3    = (const float*)d_in[10];
    const float* b3    = (const float*)d_in[11];
    float* out = (float*)d_out;

    const int nNodes = in_sizes[0];
    const int nRows  = nNodes * L;
    const int nT32   = (nRows + ROWS_W - 1) / ROWS_W;
    const int grid2  = (nNodes + 7) / 8;
    const int nCn    = (nNodes + 7) / 8;

    cudaFuncSetAttribute(mlp_score_kernel,
                         cudaFuncAttributeMaxDynamicSharedMemorySize, SMEM_BYTES);

    prep_all_kernel<<<nCn + 48, 256>>>(nodes, v2e, W1, W2, b1, b2, w3, b3,
                                       nNodes, nCn);
    mlp_score_kernel<<<GRID1, 32 * WARPS1, SMEM_BYTES>>>(
        hva, haf, a2e, f2e, nT32, nNodes, nRows);
    softmax_agg_kernel<<<grid2, 256>>>(hva, a2e, out, nNodes);
}